// round 1
// baseline (speedup 1.0000x reference)
#include <cuda_runtime.h>

#define NPATCH 2048
#define SSTR 65
#define HS (64 * SSTR)
#define SMEM_BYTES (7 * 64 * SSTR * 4)

// scratch (no device allocations allowed)
__device__ float g_ssim[NPATCH * 3];
__device__ float g_bgA[NPATCH * 2];

// ---------------------------------------------------------------------------
// Kernel 1: per-(patch, channel) SSIM partial sum.
// Block = 256 threads. Grid = (2048, 3).
// Separable 11-tap Gaussian, zero 'same' padding, all 5 conv quantities fused.
// ---------------------------------------------------------------------------
__global__ __launch_bounds__(256, 1)
void ssim_kernel(const float* __restrict__ Nn, const float* __restrict__ GT)
{
    extern __shared__ float sm[];
    float* xs = sm;             // 64 x 65
    float* ys = sm + HS;        // 64 x 65
    float* h  = sm + 2 * HS;    // 5 arrays of 64 x 65: h[q*HS + ...]

    const int t  = threadIdx.x;
    const int bp = blockIdx.x;      // patch index 0..2047
    const int ch = blockIdx.y;      // channel 0..2
    const int b  = bp >> 6;
    const int p  = bp & 63;
    const int pr = p >> 3;
    const int pc = p & 7;
    const size_t base = ((size_t)(b * 3 + ch) * 512 + (size_t)pr * 64) * 512 + (size_t)pc * 64;

    // ---- load both 64x64 tiles (float4, coalesced) ----
#pragma unroll
    for (int k = 0; k < 4; k++) {
        int idx = t + 256 * k;              // 0..1023 float4 slots
        int row = idx >> 4;
        int c4  = (idx & 15) << 2;
        const float4 xv = *(const float4*)(Nn + base + (size_t)row * 512 + c4);
        const float4 yv = *(const float4*)(GT + base + (size_t)row * 512 + c4);
        float* xd = xs + row * SSTR + c4;
        xd[0] = xv.x; xd[1] = xv.y; xd[2] = xv.z; xd[3] = xv.w;
        float* yd = ys + row * SSTR + c4;
        yd[0] = yv.x; yd[1] = yv.y; yd[2] = yv.z; yd[3] = yv.w;
    }
    __syncthreads();

    // Gaussian weights as compile-time literals -> FFMA-imm (rt_SMSP=1)
    const float gw[11] = {
        0.00102838f, 0.00759876f, 0.03600077f, 0.10936069f, 0.21300554f,
        0.26601172f,
        0.21300554f, 0.10936069f, 0.03600077f, 0.00759876f, 0.00102838f };

    // ---- horizontal pass: thread owns 16-px strip of one row ----
    {
        const int r  = t >> 2;
        const int c0 = (t & 3) << 4;
        float a0[16], a1[16], a2[16], a3[16], a4[16];
#pragma unroll
        for (int j = 0; j < 16; j++) { a0[j] = a1[j] = a2[j] = a3[j] = a4[j] = 0.f; }

#pragma unroll
        for (int i = 0; i < 26; i++) {
            int c = c0 + i - 5;
            float xv = 0.f, yv = 0.f;
            if (c >= 0 && c < 64) {
                xv = xs[r * SSTR + c];
                yv = ys[r * SSTR + c];
            }
            float xx = xv * xv, yy = yv * yv, xy = xv * yv;
#pragma unroll
            for (int j = 0; j < 16; j++) {
                int k = i - j;
                if (k >= 0 && k <= 10) {
                    a0[j] += gw[k] * xv;
                    a1[j] += gw[k] * yv;
                    a2[j] += gw[k] * xx;
                    a3[j] += gw[k] * yy;
                    a4[j] += gw[k] * xy;
                }
            }
        }
#pragma unroll
        for (int j = 0; j < 16; j++) {
            int o = r * SSTR + c0 + j;
            h[0 * HS + o] = a0[j];
            h[1 * HS + o] = a1[j];
            h[2 * HS + o] = a2[j];
            h[3 * HS + o] = a3[j];
            h[4 * HS + o] = a4[j];
        }
    }
    __syncthreads();

    // ---- vertical pass + per-pixel SSIM: thread owns 16-row strip of one col ----
    float ssum = 0.f;
    {
        const int c  = t & 63;
        const int r0 = (t >> 6) << 4;
        float a0[16], a1[16], a2[16], a3[16], a4[16];
#pragma unroll
        for (int j = 0; j < 16; j++) { a0[j] = a1[j] = a2[j] = a3[j] = a4[j] = 0.f; }

#pragma unroll
        for (int i = 0; i < 26; i++) {
            int rr = r0 + i - 5;
            float v0 = 0.f, v1 = 0.f, v2 = 0.f, v3 = 0.f, v4 = 0.f;
            if (rr >= 0 && rr < 64) {
                int o = rr * SSTR + c;
                v0 = h[0 * HS + o];
                v1 = h[1 * HS + o];
                v2 = h[2 * HS + o];
                v3 = h[3 * HS + o];
                v4 = h[4 * HS + o];
            }
#pragma unroll
            for (int j = 0; j < 16; j++) {
                int k = i - j;
                if (k >= 0 && k <= 10) {
                    a0[j] += gw[k] * v0;
                    a1[j] += gw[k] * v1;
                    a2[j] += gw[k] * v2;
                    a3[j] += gw[k] * v3;
                    a4[j] += gw[k] * v4;
                }
            }
        }

#pragma unroll
        for (int j = 0; j < 16; j++) {
            float mu1 = a0[j], mu2 = a1[j];
            float mu1sq = mu1 * mu1;
            float mu2sq = mu2 * mu2;
            float mu12  = mu1 * mu2;
            float s1  = a2[j] - mu1sq;
            float s2  = a3[j] - mu2sq;
            float s12 = a4[j] - mu12;
            float num = (2.f * mu12 + 1e-4f) * (2.f * s12 + 9e-4f);
            float den = (mu1sq + mu2sq + 1e-4f) * (s1 + s2 + 9e-4f);
            ssum += __fdividef(num, den);
        }
    }

    // ---- block reduce ssum ----
#pragma unroll
    for (int o = 16; o; o >>= 1) ssum += __shfl_xor_sync(0xffffffffu, ssum, o);
    __shared__ float red[8];
    if ((t & 31) == 0) red[t >> 5] = ssum;
    __syncthreads();
    if (t == 0) {
        float s = 0.f;
#pragma unroll
        for (int w = 0; w < 8; w++) s += red[w];
        g_ssim[bp * 3 + ch] = s;
    }
}

// ---------------------------------------------------------------------------
// Kernel 2: per-patch MSE sums for (BG-G)^2 and (A-G)^2. Grid = 2048.
// ---------------------------------------------------------------------------
__global__ __launch_bounds__(256, 1)
void mse_kernel(const float* __restrict__ A, const float* __restrict__ G,
                const float* __restrict__ BG)
{
    const int t  = threadIdx.x;
    const int bp = blockIdx.x;
    const int b  = bp >> 6;
    const int p  = bp & 63;
    const int pr = p >> 3;
    const int pc = p & 7;
    const size_t base0 = ((size_t)(b * 3) * 512 + (size_t)pr * 64) * 512 + (size_t)pc * 64;

    float sbg = 0.f, sa = 0.f;
#pragma unroll
    for (int k = 0; k < 12; k++) {
        int idx = t + 256 * k;              // 0..3071 float4 slots
        int chn = idx >> 10;
        int rem = idx & 1023;
        int row = rem >> 4;
        int c4  = (rem & 15) << 2;
        size_t off = base0 + (size_t)chn * 512 * 512 + (size_t)row * 512 + c4;
        float4 av = *(const float4*)(A + off);
        float4 gv = *(const float4*)(G + off);
        float4 bv = *(const float4*)(BG + off);
        float d;
        d = bv.x - gv.x; sbg += d * d;
        d = bv.y - gv.y; sbg += d * d;
        d = bv.z - gv.z; sbg += d * d;
        d = bv.w - gv.w; sbg += d * d;
        d = av.x - gv.x; sa += d * d;
        d = av.y - gv.y; sa += d * d;
        d = av.z - gv.z; sa += d * d;
        d = av.w - gv.w; sa += d * d;
    }

#pragma unroll
    for (int o = 16; o; o >>= 1) {
        sbg += __shfl_xor_sync(0xffffffffu, sbg, o);
        sa  += __shfl_xor_sync(0xffffffffu, sa,  o);
    }
    __shared__ float r1[8], r2[8];
    if ((t & 31) == 0) { r1[t >> 5] = sbg; r2[t >> 5] = sa; }
    __syncthreads();
    if (t == 0) {
        float x = 0.f, y = 0.f;
#pragma unroll
        for (int w = 0; w < 8; w++) { x += r1[w]; y += r2[w]; }
        g_bgA[bp]          = x;
        g_bgA[NPATCH + bp] = y;
    }
}

// ---------------------------------------------------------------------------
// Kernel 3: combine per-patch pieces into the final scalar.
// ---------------------------------------------------------------------------
__global__ __launch_bounds__(256, 1)
void final_kernel(float* __restrict__ out)
{
    const int t = threadIdx.x;
    const float inv = 1.f / 12288.f;
    float acc = 0.f;
    for (int p = t; p < NPATCH; p += 256) {
        float s = (g_ssim[3 * p] + g_ssim[3 * p + 1] + g_ssim[3 * p + 2]) * inv;
        float diff = fminf(1.f - s, 1.f);
        acc += diff * (g_bgA[p] * inv) + (1.f - diff) * (g_bgA[NPATCH + p] * inv);
    }
#pragma unroll
    for (int o = 16; o; o >>= 1) acc += __shfl_xor_sync(0xffffffffu, acc, o);
    __shared__ float red[8];
    if ((t & 31) == 0) red[t >> 5] = acc;
    __syncthreads();
    if (t == 0) {
        float s = 0.f;
#pragma unroll
        for (int w = 0; w < 8; w++) s += red[w];
        out[0] = s;
    }
}

// ---------------------------------------------------------------------------
extern "C" void kernel_launch(void* const* d_in, const int* in_sizes, int n_in,
                              void* d_out, int out_size)
{
    const float* A  = (const float*)d_in[0];
    const float* Nn = (const float*)d_in[1];
    const float* GT = (const float*)d_in[2];
    const float* G  = (const float*)d_in[3];
    const float* BG = (const float*)d_in[4];

    cudaFuncSetAttribute(ssim_kernel, cudaFuncAttributeMaxDynamicSharedMemorySize, SMEM_BYTES);

    ssim_kernel<<<dim3(NPATCH, 3), 256, SMEM_BYTES>>>(Nn, GT);
    mse_kernel<<<NPATCH, 256>>>(A, G, BG);
    final_kernel<<<1, 256>>>((float*)d_out);
}

// round 2
// speedup vs baseline: 1.3760x; 1.3760x over previous
#include <cuda_runtime.h>

#define NPATCH 2048
#define XSTR 150                     // floats per row of interleaved xy tile (74 pairs)
#define H01_OFF 0                    // 8192 floats: packed (q0,q1) pairs, 4096 x 8B
#define H23_OFF 8192                 // 8192 floats: packed (q2,q3) pairs
#define HC_OFF  16384                // region C: xy tile (64*150=9600 floats) aliased with h4 (4096 floats)
#define SMEM_FLOATS (16384 + 9600)
#define SMEM_BYTES (SMEM_FLOATS * 4) // 103,936 B -> 2 CTAs/SM

__device__ float g_ssim[NPATCH * 3];
__device__ float g_bg[NPATCH * 3];
__device__ float g_a[NPATCH * 3];

// ---- packed f32x2 helpers (sm_100+) ----
__device__ __forceinline__ unsigned long long pack2(float lo, float hi) {
    unsigned long long r;
    asm("mov.b64 %0, {%1, %2};" : "=l"(r) : "f"(lo), "f"(hi));
    return r;
}
__device__ __forceinline__ void unpack2(unsigned long long v, float& lo, float& hi) {
    asm("mov.b64 {%0, %1}, %2;" : "=f"(lo), "=f"(hi) : "l"(v));
}
__device__ __forceinline__ unsigned long long fma2(unsigned long long a, unsigned long long b,
                                                   unsigned long long c) {
    unsigned long long d;
    asm("fma.rn.f32x2 %0, %1, %2, %3;" : "=l"(d) : "l"(a), "l"(b), "l"(c));
    return d;
}
__device__ __forceinline__ unsigned long long mul2(unsigned long long a, unsigned long long b) {
    unsigned long long d;
    asm("mul.rn.f32x2 %0, %1, %2;" : "=l"(d) : "l"(a), "l"(b));
    return d;
}

// ---------------------------------------------------------------------------
// Fused kernel: per-(patch, channel) SSIM partial sum + MSE partial sums.
// Block = 256 threads. Grid = (2048, 3).
// ---------------------------------------------------------------------------
__global__ __launch_bounds__(256, 2)
void ssim_kernel(const float* __restrict__ Nn, const float* __restrict__ GT,
                 const float* __restrict__ A, const float* __restrict__ G,
                 const float* __restrict__ BG)
{
    extern __shared__ float sm[];
    unsigned long long* h01 = (unsigned long long*)(sm + H01_OFF);
    unsigned long long* h23 = (unsigned long long*)(sm + H23_OFF);

    const int t  = threadIdx.x;
    const int bp = blockIdx.x;      // patch index 0..2047
    const int ch = blockIdx.y;      // channel 0..2
    const int b  = bp >> 6;
    const int p  = bp & 63;
    const int pr = p >> 3;
    const int pc = p & 7;
    const size_t base = ((size_t)(b * 3 + ch) * 512 + (size_t)pr * 64) * 512 + (size_t)pc * 64;

    const float gwa[11] = {
        0.00102838f, 0.00759876f, 0.03600077f, 0.10936069f, 0.21300554f,
        0.26601172f,
        0.21300554f, 0.10936069f, 0.03600077f, 0.00759876f, 0.00102838f };
    unsigned long long W2[11];
#pragma unroll
    for (int k = 0; k < 11; k++) W2[k] = pack2(gwa[k], gwa[k]);

    // ---- zero the 5-pair left/right padding columns of the xy tile ----
    for (int z = t; z < 640; z += 256) {
        int r = z / 10, q = z % 10;
        int cp = (q < 5) ? q : (q + 64);       // pair index 0..4 and 69..73
        int o = HC_OFF + r * XSTR + cp * 2;
        sm[o] = 0.f; sm[o + 1] = 0.f;
    }
    // ---- load both 64x64 tiles, interleaved as (x,y) pairs ----
#pragma unroll
    for (int k = 0; k < 4; k++) {
        int idx = t + 256 * k;                 // 0..1023 float4 slots
        int row = idx >> 4;
        int c4  = (idx & 15) << 2;
        const float4 xv = *(const float4*)(Nn + base + (size_t)row * 512 + c4);
        const float4 yv = *(const float4*)(GT + base + (size_t)row * 512 + c4);
        float2* dst = (float2*)(sm + HC_OFF + row * XSTR + (c4 + 5) * 2);
        dst[0] = make_float2(xv.x, yv.x);
        dst[1] = make_float2(xv.y, yv.y);
        dst[2] = make_float2(xv.z, yv.z);
        dst[3] = make_float2(xv.w, yv.w);
    }
    __syncthreads();

    // ---- horizontal pass: thread owns 16-px strip of row r ----
    {
        const int r  = t & 63;
        const int c0 = (t >> 6) << 4;
        unsigned long long A01[16], A23[16];
        float A4[16];
#pragma unroll
        for (int j = 0; j < 16; j++) { A01[j] = 0ull; A23[j] = 0ull; A4[j] = 0.f; }

#pragma unroll
        for (int i = 0; i < 26; i++) {
            unsigned long long pxy =
                *(const unsigned long long*)(sm + HC_OFF + r * XSTR + (c0 + i) * 2);
            unsigned long long pxx = mul2(pxy, pxy);
            float xv, yv; unpack2(pxy, xv, yv);
            float sxy = xv * yv;
#pragma unroll
            for (int j = 0; j < 16; j++) {
                int k = i - j;
                if (k >= 0 && k < 11) {
                    A01[j] = fma2(pxy, W2[k], A01[j]);
                    A23[j] = fma2(pxx, W2[k], A23[j]);
                    A4[j]  = fmaf(sxy, gwa[k], A4[j]);
                }
            }
        }
        // write h01/h23 (do not alias xy)
#pragma unroll
        for (int j = 0; j < 16; j++) {
            int c = c0 + j;
            int d = (c << 6) + (r ^ (c & 15));
            h01[d] = A01[j];
            h23[d] = A23[j];
        }
        __syncthreads();   // all xy reads complete before h4 overwrites region C
#pragma unroll
        for (int j = 0; j < 16; j++) {
            int c = c0 + j;
            sm[HC_OFF + (c << 6) + (r ^ (c & 31))] = A4[j];
        }
    }
    __syncthreads();

    // ---- vertical pass + per-pixel SSIM: thread owns 16-row strip of col c ----
    float ssum = 0.f;
    {
        const int c  = t & 63;
        const int r0 = (t >> 6) << 4;
        unsigned long long B01[16], B23[16];
        float B4[16];
#pragma unroll
        for (int j = 0; j < 16; j++) { B01[j] = 0ull; B23[j] = 0ull; B4[j] = 0.f; }

#pragma unroll
        for (int i = 0; i < 26; i++) {
            int rr = r0 + i - 5;
            if (rr >= 0 && rr < 64) {          // uniform per warp
                int d = (c << 6) + (rr ^ (c & 15));
                unsigned long long p01 = h01[d];
                unsigned long long p23 = h23[d];
                float v4 = sm[HC_OFF + (c << 6) + (rr ^ (c & 31))];
#pragma unroll
                for (int j = 0; j < 16; j++) {
                    int k = i - j;
                    if (k >= 0 && k < 11) {
                        B01[j] = fma2(p01, W2[k], B01[j]);
                        B23[j] = fma2(p23, W2[k], B23[j]);
                        B4[j]  = fmaf(v4, gwa[k], B4[j]);
                    }
                }
            }
        }

#pragma unroll
        for (int j = 0; j < 16; j++) {
            float mu1, mu2; unpack2(B01[j], mu1, mu2);
            float ex2, ey2; unpack2(B23[j], ex2, ey2);
            float mu1sq = mu1 * mu1;
            float mu2sq = mu2 * mu2;
            float mu12  = mu1 * mu2;
            float s1  = ex2 - mu1sq;
            float s2  = ey2 - mu2sq;
            float s12 = B4[j] - mu12;
            float num = (2.f * mu12 + 1e-4f) * (2.f * s12 + 9e-4f);
            float den = (mu1sq + mu2sq + 1e-4f) * (s1 + s2 + 9e-4f);
            ssum += __fdividef(num, den);
        }
    }

    // ---- fused per-tile MSE sums: (BG-G)^2 and (A-G)^2 ----
    float sbg = 0.f, sa = 0.f;
#pragma unroll
    for (int k = 0; k < 4; k++) {
        int idx = t + 256 * k;
        int row = idx >> 4;
        int c4  = (idx & 15) << 2;
        size_t off = base + (size_t)row * 512 + c4;
        float4 av = *(const float4*)(A + off);
        float4 gv = *(const float4*)(G + off);
        float4 bv = *(const float4*)(BG + off);
        float d;
        d = bv.x - gv.x; sbg += d * d;
        d = bv.y - gv.y; sbg += d * d;
        d = bv.z - gv.z; sbg += d * d;
        d = bv.w - gv.w; sbg += d * d;
        d = av.x - gv.x; sa += d * d;
        d = av.y - gv.y; sa += d * d;
        d = av.z - gv.z; sa += d * d;
        d = av.w - gv.w; sa += d * d;
    }

    // ---- block reduce (ssum, sbg, sa) ----
#pragma unroll
    for (int o = 16; o; o >>= 1) {
        ssum += __shfl_xor_sync(0xffffffffu, ssum, o);
        sbg  += __shfl_xor_sync(0xffffffffu, sbg,  o);
        sa   += __shfl_xor_sync(0xffffffffu, sa,   o);
    }
    __shared__ float red[24];
    if ((t & 31) == 0) {
        red[(t >> 5)]      = ssum;
        red[(t >> 5) + 8]  = sbg;
        red[(t >> 5) + 16] = sa;
    }
    __syncthreads();
    if (t == 0) {
        float s0 = 0.f, s1 = 0.f, s2 = 0.f;
#pragma unroll
        for (int w = 0; w < 8; w++) { s0 += red[w]; s1 += red[w + 8]; s2 += red[w + 16]; }
        int o3 = bp * 3 + ch;
        g_ssim[o3] = s0;
        g_bg[o3]   = s1;
        g_a[o3]    = s2;
    }
}

// ---------------------------------------------------------------------------
// Final combine into the scalar output.
// ---------------------------------------------------------------------------
__global__ __launch_bounds__(256, 1)
void final_kernel(float* __restrict__ out)
{
    const int t = threadIdx.x;
    const float inv = 1.f / 12288.f;
    float acc = 0.f;
    for (int p = t; p < NPATCH; p += 256) {
        float s  = (g_ssim[3 * p] + g_ssim[3 * p + 1] + g_ssim[3 * p + 2]) * inv;
        float bg = (g_bg[3 * p]   + g_bg[3 * p + 1]   + g_bg[3 * p + 2])   * inv;
        float a  = (g_a[3 * p]    + g_a[3 * p + 1]    + g_a[3 * p + 2])    * inv;
        float diff = fminf(1.f - s, 1.f);
        acc += diff * bg + (1.f - diff) * a;
    }
#pragma unroll
    for (int o = 16; o; o >>= 1) acc += __shfl_xor_sync(0xffffffffu, acc, o);
    __shared__ float red[8];
    if ((t & 31) == 0) red[t >> 5] = acc;
    __syncthreads();
    if (t == 0) {
        float s = 0.f;
#pragma unroll
        for (int w = 0; w < 8; w++) s += red[w];
        out[0] = s;
    }
}

// ---------------------------------------------------------------------------
extern "C" void kernel_launch(void* const* d_in, const int* in_sizes, int n_in,
                              void* d_out, int out_size)
{
    const float* A  = (const float*)d_in[0];
    const float* Nn = (const float*)d_in[1];
    const float* GT = (const float*)d_in[2];
    const float* G  = (const float*)d_in[3];
    const float* BG = (const float*)d_in[4];

    cudaFuncSetAttribute(ssim_kernel, cudaFuncAttributeMaxDynamicSharedMemorySize, SMEM_BYTES);

    ssim_kernel<<<dim3(NPATCH, 3), 256, SMEM_BYTES>>>(Nn, GT, A, G, BG);
    final_kernel<<<1, 256>>>((float*)d_out);
}